// round 13
// baseline (speedup 1.0000x reference)
#include <cuda_runtime.h>
#include <cstdint>
#include <math.h>

#define IN_DIM 256
#define HIDDEN 64
#define MAX_NODES 100000
#define NT 512
#define NB2 148                 // K2: one wave, guaranteed co-resident (proven R12)
#define NTH2 (NB2 * NT)

// Pipeline state (allocation-free: __device__ globals)
__device__ float g_z[MAX_NODES];      // x @ wv
__device__ float g_zs[MAX_NODES];     // dinv * z
__device__ float g_dinv[MAX_NODES];   // (deg+1)^-1/2
__device__ float g_aggs[MAX_NODES];   // edge-sum aggregate
__device__ int   g_degcnt[MAX_NODES]; // zeroed via cudaMemsetAsync each call

// Software grid barrier (generation counter; survives graph replays)
__device__ unsigned g_count;
__device__ volatile unsigned g_gen;

__device__ __forceinline__ void gbar() {
    __syncthreads();
    if (threadIdx.x == 0) {
        __threadfence();
        unsigned gen = g_gen;
        if (atomicAdd(&g_count, 1u) == NB2 - 1) {
            g_count = 0;
            __threadfence();
            g_gen = gen + 1;
        } else {
            while (g_gen == gen) { __nanosleep(64); }
        }
        __threadfence();
    }
    __syncthreads();
}

__device__ __forceinline__ int probe_stride(const int* __restrict__ ei) {
    // JAX usually demotes int64->int32; for int64 LE (<2^31) odd words are 0.
    int nz = 0;
    #pragma unroll
    for (int i = 1; i < 128; i += 2) nz |= ei[i];
    return (nz == 0) ? 2 : 1;
}

// ---------------------------------------------------------------------------
// K1 (full-width): z = x@wv  +  degree histogram  +  zero aggs  (independent)
// grid = ceil(n/16) blocks x 512. Warp-per-row z; strided int4 edge atomics.
// ---------------------------------------------------------------------------
__global__ void __launch_bounds__(NT)
k1(const float* __restrict__ x, const int* __restrict__ ei,
   const float* __restrict__ W, const float* __restrict__ w2, int n, int E) {
    __shared__ float swv[IN_DIM];
    __shared__ int s_st;

    const int tid = threadIdx.x;
    const int nth = gridDim.x * NT;
    const int gtid = blockIdx.x * NT + tid;

    if (tid < IN_DIM) {
        float s = 0.0f;
        #pragma unroll 8
        for (int j = 0; j < HIDDEN; j++) s = fmaf(W[tid * HIDDEN + j], w2[j], s);
        swv[tid] = s;
    }
    if (tid == 0) s_st = probe_stride(ei);
    // zero aggs (consumed only in K2 -> no hazard)
    for (int i = gtid; i < n; i += nth) g_aggs[i] = 0.0f;
    __syncthreads();
    const int st = s_st;

    // ---- z matvec: warp per row, 2x float4 per lane (coalesced) ----
    {
        const int lane = tid & 31;
        const int row = blockIdx.x * 16 + (tid >> 5);
        if (row < n) {
            const float4* wv4 = reinterpret_cast<const float4*>(swv);
            float4 w0 = wv4[lane], w1 = wv4[lane + 32];
            const float4* xr = reinterpret_cast<const float4*>(x + (size_t)row * IN_DIM);
            float4 a = xr[lane], c = xr[lane + 32];
            float p = a.x * w0.x + a.y * w0.y + a.z * w0.z + a.w * w0.w
                    + c.x * w1.x + c.y * w1.y + c.z * w1.z + c.w * w1.w;
            #pragma unroll
            for (int o = 16; o; o >>= 1) p += __shfl_xor_sync(0xffffffffu, p, o);
            if (lane == 0) g_z[row] = p;
        }
    }

    // ---- degree histogram over dst row (independent of z) ----
    if (st == 1) {
        const int4* d4p = reinterpret_cast<const int4*>(ei + E);
        int nc = E >> 2;
        for (int c = gtid; c < nc; c += nth) {
            int4 d4 = d4p[c];
            atomicAdd(&g_degcnt[d4.x], 1);
            atomicAdd(&g_degcnt[d4.y], 1);
            atomicAdd(&g_degcnt[d4.z], 1);
            atomicAdd(&g_degcnt[d4.w], 1);
        }
        for (int e = (nc << 2) + gtid; e < E; e += nth)
            atomicAdd(&g_degcnt[ei[E + e]], 1);
    } else {
        for (int e = gtid; e < E; e += nth)
            atomicAdd(&g_degcnt[ei[(size_t)2 * (E + e)]], 1);
    }
}

// ---------------------------------------------------------------------------
// K2 (persistent, 148x512): dinv/zs -> gbar -> scatter -> gbar -> sigmoid out
// All phases are short or atomic-bound; 16 warps/SM suffices here.
// ---------------------------------------------------------------------------
__global__ void __launch_bounds__(NT, 1)
k2(const int* __restrict__ ei, const float* __restrict__ b,
   const float* __restrict__ w2, const float* __restrict__ b2,
   float* __restrict__ out, int n, int E) {
    __shared__ float s_cst;
    __shared__ int s_st;
    const int tid = threadIdx.x;
    const int gtid = blockIdx.x * NT + tid;

    if (tid == 0) {
        float c = b2[0];
        for (int j = 0; j < HIDDEN; j++) c = fmaf(b[j], w2[j], c);
        s_cst = c;
        s_st = probe_stride(ei);
    }
    __syncthreads();
    const int st = s_st;

    // ---- phase 0: dinv = rsqrt(deg+1); zs = dinv*z ----
    for (int i = gtid; i < n; i += NTH2) {
        float dv = rsqrtf((float)g_degcnt[i] + 1.0f);
        g_dinv[i] = dv;
        g_zs[i] = dv * g_z[i];
    }
    gbar();

    // ---- phase 1: scatter aggs[d] += zs[s] * dinv[d] (scalar fp32 RED) ----
    if (st == 1) {
        const int4* s4p = reinterpret_cast<const int4*>(ei);
        const int4* d4p = reinterpret_cast<const int4*>(ei + E);
        int nc = E >> 2;
        for (int c = gtid; c < nc; c += NTH2) {
            int4 s4 = s4p[c];
            int4 d4 = d4p[c];
            atomicAdd(&g_aggs[d4.x], g_zs[s4.x] * g_dinv[d4.x]);
            atomicAdd(&g_aggs[d4.y], g_zs[s4.y] * g_dinv[d4.y]);
            atomicAdd(&g_aggs[d4.z], g_zs[s4.z] * g_dinv[d4.z]);
            atomicAdd(&g_aggs[d4.w], g_zs[s4.w] * g_dinv[d4.w]);
        }
        for (int e = (nc << 2) + gtid; e < E; e += NTH2) {
            int s = ei[e], d = ei[E + e];
            atomicAdd(&g_aggs[d], g_zs[s] * g_dinv[d]);
        }
    } else {
        for (int e = gtid; e < E; e += NTH2) {
            int s = ei[(size_t)2 * e];
            int d = ei[(size_t)2 * (E + e)];
            atomicAdd(&g_aggs[d], g_zs[s] * g_dinv[d]);
        }
    }
    gbar();

    // ---- phase 2: out = sigmoid(aggs + dinv*zs + cst) ----
    const float cst = s_cst;
    for (int i = gtid; i < n; i += NTH2) {
        float zv = g_aggs[i] + g_dinv[i] * g_zs[i] + cst;
        out[i] = 1.0f / (1.0f + __expf(-zv));
    }
}

// ---------------------------------------------------------------------------
extern "C" void kernel_launch(void* const* d_in, const int* in_sizes, int n_in,
                              void* d_out, int out_size) {
    const float* x  = (const float*)d_in[0];
    const int*   ei = (const int*)d_in[1];      // int32 words (or int64 pairs)
    const float* W  = (const float*)d_in[2];
    const float* b  = (const float*)d_in[3];
    const float* w2 = (const float*)d_in[4];
    const float* b2 = (const float*)d_in[5];
    float* out = (float*)d_out;

    int n = in_sizes[0] / IN_DIM;     // 100000
    int E = in_sizes[1] / 2;          // 1600000 elements per row

    // degcnt must be zero before K1's atomics: one async memset graph node.
    void* degp = nullptr;
    cudaGetSymbolAddress(&degp, g_degcnt);
    cudaMemsetAsync(degp, 0, (size_t)n * sizeof(int));

    k1<<<(n + 15) / 16, NT>>>(x, ei, W, w2, n, E);
    k2<<<NB2, NT>>>(ei, b, w2, b2, out, n, E);
}

// round 15
// speedup vs baseline: 6.3611x; 6.3611x over previous
#include <cuda_runtime.h>
#include <cstdint>
#include <math.h>

#define IN_DIM 256
#define HIDDEN 64
#define MAX_NODES 100000
#define NT 512

// Pipeline state (allocation-free: __device__ globals)
__device__ float g_wv[IN_DIM];        // W @ w2 (computed ONCE in init)
__device__ float g_cst;               // b.w2 + b2
__device__ float g_z[MAX_NODES];      // x @ wv
__device__ float g_zs[MAX_NODES];     // dinv * z
__device__ float g_dinv[MAX_NODES];   // (deg+1)^-1/2
__device__ float g_aggs[MAX_NODES];   // SUM of zs[s] over in-edges (unscaled!)
__device__ int   g_degcnt[MAX_NODES]; // zeroed via cudaMemsetAsync
__device__ int   g_stride;            // 1 = int32 edge_index, 2 = int64

// ---------------------------------------------------------------------------
// init (1 block): wv = W@w2, cst = b.w2+b2, dtype probe. ~2 us.
// ---------------------------------------------------------------------------
__global__ void init_kernel(const int* __restrict__ ei, const float* __restrict__ W,
                            const float* __restrict__ b, const float* __restrict__ w2,
                            const float* __restrict__ b2) {
    int k = threadIdx.x;
    float s = 0.0f;
    #pragma unroll 8
    for (int j = 0; j < HIDDEN; j++) s = fmaf(W[k * HIDDEN + j], w2[j], s);
    g_wv[k] = s;
    if (k == 0) {
        float c = b2[0];
        for (int j = 0; j < HIDDEN; j++) c = fmaf(b[j], w2[j], c);
        g_cst = c;
        int nz = 0;   // int64 LE (<2^31): odd 32-bit words all zero
        #pragma unroll
        for (int i = 1; i < 128; i += 2) nz |= ei[i];
        g_stride = (nz == 0) ? 2 : 1;
    }
}

// ---------------------------------------------------------------------------
// k1 (full width): z = x@wv (warp/row, DRAM-bound)  +  degree histogram
// (LTS-atomic-bound)  +  zero aggs. swv loaded COALESCED from g_wv (1 KB).
// ---------------------------------------------------------------------------
__global__ void __launch_bounds__(NT)
k1(const float* __restrict__ x, const int* __restrict__ ei, int n, int E) {
    __shared__ float4 swv[IN_DIM / 4];
    const int tid  = threadIdx.x;
    const int nth  = gridDim.x * NT;
    const int gtid = blockIdx.x * NT + tid;

    if (tid < IN_DIM / 4)
        swv[tid] = reinterpret_cast<const float4*>(g_wv)[tid];
    for (int i = gtid; i < n; i += nth) g_aggs[i] = 0.0f;   // consumed only later
    __syncthreads();
    const int st = g_stride;

    // ---- z matvec: warp per row, 2x float4 per lane (coalesced) ----
    {
        const int lane = tid & 31;
        const int row = blockIdx.x * 16 + (tid >> 5);
        if (row < n) {
            float4 w0 = swv[lane], w1 = swv[lane + 32];
            const float4* xr = reinterpret_cast<const float4*>(x + (size_t)row * IN_DIM);
            float4 a = xr[lane], c = xr[lane + 32];
            float p = a.x * w0.x + a.y * w0.y + a.z * w0.z + a.w * w0.w
                    + c.x * w1.x + c.y * w1.y + c.z * w1.z + c.w * w1.w;
            #pragma unroll
            for (int o = 16; o; o >>= 1) p += __shfl_xor_sync(0xffffffffu, p, o);
            if (lane == 0) g_z[row] = p;
        }
    }

    // ---- degree histogram over dst row ----
    if (st == 1) {
        const int4* d4p = reinterpret_cast<const int4*>(ei + E);
        int nc = E >> 2;
        for (int c = gtid; c < nc; c += nth) {
            int4 d4 = d4p[c];
            atomicAdd(&g_degcnt[d4.x], 1);
            atomicAdd(&g_degcnt[d4.y], 1);
            atomicAdd(&g_degcnt[d4.z], 1);
            atomicAdd(&g_degcnt[d4.w], 1);
        }
        for (int e = (nc << 2) + gtid; e < E; e += nth)
            atomicAdd(&g_degcnt[ei[E + e]], 1);
    } else {
        for (int e = gtid; e < E; e += nth)
            atomicAdd(&g_degcnt[ei[(size_t)2 * (E + e)]], 1);
    }
}

// ---------------------------------------------------------------------------
// k2: dinv = rsqrt(deg+1); zs = dinv*z
// ---------------------------------------------------------------------------
__global__ void k2(int n) {
    int i = blockIdx.x * blockDim.x + threadIdx.x;
    if (i >= n) return;
    float dv = rsqrtf((float)g_degcnt[i] + 1.0f);
    g_dinv[i] = dv;
    g_zs[i] = dv * g_z[i];
}

// ---------------------------------------------------------------------------
// k3: scatter — aggs[d] += zs[s] ONLY (dinv[d] factored out: applied in k4).
// 2 memory ops per edge: one zs gather + one scalar fp32 RED.
// ---------------------------------------------------------------------------
__global__ void k3(const int* __restrict__ ei, int E) {
    int t = blockIdx.x * blockDim.x + threadIdx.x;
    int st = g_stride;
    if (st == 1) {
        int e0 = t * 4;
        if (e0 >= E) return;
        if (e0 + 4 <= E) {
            int4 s4 = *reinterpret_cast<const int4*>(ei + e0);
            int4 d4 = *reinterpret_cast<const int4*>(ei + E + e0);
            atomicAdd(&g_aggs[d4.x], g_zs[s4.x]);
            atomicAdd(&g_aggs[d4.y], g_zs[s4.y]);
            atomicAdd(&g_aggs[d4.z], g_zs[s4.z]);
            atomicAdd(&g_aggs[d4.w], g_zs[s4.w]);
        } else {
            for (int e = e0; e < E; e++)
                atomicAdd(&g_aggs[ei[E + e]], g_zs[ei[e]]);
        }
    } else {
        int e0 = t * 4;
        int lim = (e0 + 4 < E) ? e0 + 4 : E;
        for (int e = e0; e < lim; e++) {
            int s = ei[(size_t)2 * e];
            int d = ei[(size_t)2 * (E + e)];
            atomicAdd(&g_aggs[d], g_zs[s]);
        }
    }
}

// ---------------------------------------------------------------------------
// k4: out = sigmoid( dinv*(aggs + zs) + cst )
//   edge term: dinv[d]*Σ zs[s];  self loop: dinv*zs = dinv^2*z
// ---------------------------------------------------------------------------
__global__ void k4(float* __restrict__ out, int n) {
    int i = blockIdx.x * blockDim.x + threadIdx.x;
    if (i >= n) return;
    float zv = g_dinv[i] * (g_aggs[i] + g_zs[i]) + g_cst;
    out[i] = 1.0f / (1.0f + __expf(-zv));
}

// ---------------------------------------------------------------------------
extern "C" void kernel_launch(void* const* d_in, const int* in_sizes, int n_in,
                              void* d_out, int out_size) {
    const float* x  = (const float*)d_in[0];
    const int*   ei = (const int*)d_in[1];      // int32 words (or int64 pairs)
    const float* W  = (const float*)d_in[2];
    const float* b  = (const float*)d_in[3];
    const float* w2 = (const float*)d_in[4];
    const float* b2 = (const float*)d_in[5];
    float* out = (float*)d_out;

    int n = in_sizes[0] / IN_DIM;     // 100000
    int E = in_sizes[1] / 2;          // 1600000 elements per row

    void* degp = nullptr;
    cudaGetSymbolAddress(&degp, g_degcnt);
    cudaMemsetAsync(degp, 0, (size_t)n * sizeof(int));

    init_kernel<<<1, 256>>>(ei, W, b, w2, b2);
    k1<<<(n + 15) / 16, NT>>>(x, ei, n, E);
    k2<<<(n + 255) / 256, 256>>>(n);
    k3<<<(E / 4 + 255) / 256, 256>>>(ei, E);
    k4<<<(n + 255) / 256, 256>>>(out, n);
}